// round 1
// baseline (speedup 1.0000x reference)
#include <cuda_runtime.h>
#include <math.h>

#define B_  2
#define T_  1024
#define BT  2048
#define D_  768
#define H_  12
#define DH_ 64
#define FF_ 3072
#define L_  12
#define S_  8
#define V_  1024
#define E3  2304   // 3*D

// ---------------- scratch (static device arrays; no allocation allowed) ----
__device__ float g_x   [BT * D_];
__device__ float g_h   [BT * D_];
__device__ float g_qkv [BT * E3];
__device__ float g_att [BT * D_];
__device__ float g_gate[BT * FF_];
__device__ float g_up  [BT * FF_];
__device__ float g_last[B_ * D_];

// ---------------- embedding ------------------------------------------------
__global__ void embed_kernel(const int* __restrict__ tok,
                             const int* __restrict__ pos,
                             const float* __restrict__ intent,
                             const float* __restrict__ rvq,
                             const float* __restrict__ pe) {
    int i = blockIdx.x * blockDim.x + threadIdx.x;
    if (i >= BT * D_) return;
    int row = i / D_, d = i % D_;
    int b = row / T_;
    float acc = intent[b * D_ + d] + pe[(size_t)pos[row] * D_ + d];
    const int* tk = tok + (size_t)row * S_;
#pragma unroll
    for (int s = 0; s < S_; s++)
        acc += rvq[((size_t)s * V_ + tk[s]) * D_ + d];
    g_x[i] = acc;
}

// ---------------- rmsnorm (one block per row) ------------------------------
__global__ void rmsnorm_kernel(const float* __restrict__ src,
                               float* __restrict__ dst,
                               const float* __restrict__ w) {
    int row = blockIdx.x;
    const float* x = src + (size_t)row * D_;
    __shared__ float red[256];
    float ss = 0.f;
    for (int d = threadIdx.x; d < D_; d += 256) { float v = x[d]; ss += v * v; }
    red[threadIdx.x] = ss;
    __syncthreads();
    for (int s = 128; s > 0; s >>= 1) {
        if (threadIdx.x < s) red[threadIdx.x] += red[threadIdx.x + s];
        __syncthreads();
    }
    float inv = rsqrtf(red[0] * (1.0f / D_) + 1e-6f);
    for (int d = threadIdx.x; d < D_; d += 256)
        dst[(size_t)row * D_ + d] = x[d] * inv * w[d];
}

// ---------------- fp32 GEMM: C[M,N] = (res?) + A[M,K] * W[N,K]^T ----------
// 64x64 block tile, BK=16, 256 threads, 4x4 microtile, float4 everywhere.
#define BMt 64
#define BNt 64
#define BKt 16
__global__ void gemm_kernel(const float* __restrict__ A,
                            const float* __restrict__ W,
                            float* __restrict__ C,
                            const float* __restrict__ res,
                            int M, int N, int K) {
    __shared__ float As[BKt][BMt + 4];
    __shared__ float Ws[BKt][BNt + 4];
    int tid = threadIdx.x;
    int tx = tid & 15, ty = tid >> 4;
    int m0 = blockIdx.y * BMt, n0 = blockIdx.x * BNt;

    float acc[4][4] = {};
    int lm = tid >> 2;            // 0..63
    int lk = (tid & 3) * 4;       // 0,4,8,12

    for (int k0 = 0; k0 < K; k0 += BKt) {
        float4 a = *(const float4*)&A[(size_t)(m0 + lm) * K + k0 + lk];
        As[lk + 0][lm] = a.x; As[lk + 1][lm] = a.y;
        As[lk + 2][lm] = a.z; As[lk + 3][lm] = a.w;
        float4 w = *(const float4*)&W[(size_t)(n0 + lm) * K + k0 + lk];
        Ws[lk + 0][lm] = w.x; Ws[lk + 1][lm] = w.y;
        Ws[lk + 2][lm] = w.z; Ws[lk + 3][lm] = w.w;
        __syncthreads();
#pragma unroll
        for (int kk = 0; kk < BKt; kk++) {
            float4 av4 = *(const float4*)&As[kk][ty * 4];
            float4 wv4 = *(const float4*)&Ws[kk][tx * 4];
            float av[4] = {av4.x, av4.y, av4.z, av4.w};
            float wv[4] = {wv4.x, wv4.y, wv4.z, wv4.w};
#pragma unroll
            for (int i = 0; i < 4; i++)
#pragma unroll
                for (int j = 0; j < 4; j++)
                    acc[i][j] += av[i] * wv[j];
        }
        __syncthreads();
    }
#pragma unroll
    for (int i = 0; i < 4; i++) {
        int m = m0 + ty * 4 + i;
        size_t off = (size_t)m * N + n0 + tx * 4;
        float4 c = make_float4(acc[i][0], acc[i][1], acc[i][2], acc[i][3]);
        if (res) {
            float4 r = *(const float4*)&res[off];
            c.x += r.x; c.y += r.y; c.z += r.z; c.w += r.w;
        }
        *(float4*)&C[off] = c;
    }
}

// ---------------- causal attention: one block per (b,h,q) row -------------
__global__ void attn_kernel() {
    int idx = blockIdx.x;
    int q = idx % T_;
    int bh = idx / T_;
    int h = bh % H_;
    int b = bh / H_;
    int tid = threadIdx.x;   // 128

    __shared__ float q_s[DH_];
    __shared__ float sc[T_];
    __shared__ float red[128];

    if (tid < DH_)
        q_s[tid] = g_qkv[((size_t)(b * T_ + q)) * E3 + h * DH_ + tid];
    __syncthreads();

    int nk = q + 1;
    float lmax = -INFINITY;
    for (int j = tid; j < nk; j += 128) {
        const float4* kp = (const float4*)&g_qkv[((size_t)(b * T_ + j)) * E3 + D_ + h * DH_];
        const float4* qp = (const float4*)q_s;
        float dot = 0.f;
#pragma unroll
        for (int d4 = 0; d4 < DH_ / 4; d4++) {
            float4 kv = kp[d4], qv = qp[d4];
            dot += kv.x * qv.x + kv.y * qv.y + kv.z * qv.z + kv.w * qv.w;
        }
        dot *= 0.125f;   // DH^-0.5
        sc[j] = dot;
        lmax = fmaxf(lmax, dot);
    }
    red[tid] = lmax;
    __syncthreads();
    for (int s = 64; s > 0; s >>= 1) {
        if (tid < s) red[tid] = fmaxf(red[tid], red[tid + s]);
        __syncthreads();
    }
    float m = red[0];
    __syncthreads();

    float lsum = 0.f;
    for (int j = tid; j < nk; j += 128) {
        float p = expf(sc[j] - m);
        sc[j] = p;
        lsum += p;
    }
    red[tid] = lsum;
    __syncthreads();
    for (int s = 64; s > 0; s >>= 1) {
        if (tid < s) red[tid] += red[tid + s];
        __syncthreads();
    }
    float inv = 1.f / red[0];
    __syncthreads();

    int d = tid & 63, half = tid >> 6;
    float acc = 0.f;
    for (int j = half; j < nk; j += 2)
        acc += sc[j] * g_qkv[((size_t)(b * T_ + j)) * E3 + 2 * D_ + h * DH_ + d];
    red[tid] = acc;
    __syncthreads();
    if (half == 0)
        g_att[((size_t)(b * T_ + q)) * D_ + h * DH_ + d] = (red[tid] + red[tid + 64]) * inv;
}

// ---------------- silu(gate) * up ------------------------------------------
__global__ void silu_mul_kernel() {
    int i = blockIdx.x * blockDim.x + threadIdx.x;
    if (i >= BT * FF_) return;
    float g = g_gate[i];
    g_gate[i] = (g / (1.f + expf(-g))) * g_up[i];
}

// ---------------- final rmsnorm on last token rows -------------------------
__global__ void final_norm_kernel(const float* __restrict__ w) {
    int b = blockIdx.x;
    const float* x = g_x + ((size_t)(b * T_ + T_ - 1)) * D_;
    __shared__ float red[256];
    float ss = 0.f;
    for (int d = threadIdx.x; d < D_; d += 256) { float v = x[d]; ss += v * v; }
    red[threadIdx.x] = ss;
    __syncthreads();
    for (int s = 128; s > 0; s >>= 1) {
        if (threadIdx.x < s) red[threadIdx.x] += red[threadIdx.x + s];
        __syncthreads();
    }
    float inv = rsqrtf(red[0] * (1.0f / D_) + 1e-6f);
    for (int d = threadIdx.x; d < D_; d += 256)
        g_last[b * D_ + d] = x[d] * inv * w[d];
}

// ---------------- heads: logits[s,b,v] = last[b,:] . heads_w[s,v,:] --------
__global__ void heads_kernel(const float* __restrict__ hw, float* __restrict__ out) {
    int idx = blockIdx.x;           // (s*B + b)*V + v
    int v = idx % V_;
    int sb = idx / V_;
    int b = sb % B_;
    int s = sb / B_;
    const float* wrow = hw + ((size_t)s * V_ + v) * D_;
    const float* xv = g_last + b * D_;
    float dot = 0.f;
    for (int d = threadIdx.x; d < D_; d += 128) dot += xv[d] * wrow[d];
    __shared__ float red[128];
    red[threadIdx.x] = dot;
    __syncthreads();
    for (int s2 = 64; s2 > 0; s2 >>= 1) {
        if (threadIdx.x < s2) red[threadIdx.x] += red[threadIdx.x + s2];
        __syncthreads();
    }
    if (threadIdx.x == 0) out[idx] = red[0];
}

// ---------------- launcher -------------------------------------------------
extern "C" void kernel_launch(void* const* d_in, const int* in_sizes, int n_in,
                              void* d_out, int out_size) {
    const int*   tok    = (const int*)d_in[0];
    const int*   pos    = (const int*)d_in[1];
    const float* intent = (const float*)d_in[2];
    const float* rvq    = (const float*)d_in[3];
    const float* pe     = (const float*)d_in[4];
    const float* n1     = (const float*)d_in[5];
    const float* n2     = (const float*)d_in[6];
    const float* qkvw   = (const float*)d_in[7];
    const float* projw  = (const float*)d_in[8];
    const float* gatew  = (const float*)d_in[9];
    const float* upw    = (const float*)d_in[10];
    const float* downw  = (const float*)d_in[11];
    const float* nf     = (const float*)d_in[12];
    const float* hw     = (const float*)d_in[13];
    float* out = (float*)d_out;

    float *x, *h, *qkv, *att, *gate, *up;
    cudaGetSymbolAddress((void**)&x,    g_x);
    cudaGetSymbolAddress((void**)&h,    g_h);
    cudaGetSymbolAddress((void**)&qkv,  g_qkv);
    cudaGetSymbolAddress((void**)&att,  g_att);
    cudaGetSymbolAddress((void**)&gate, g_gate);
    cudaGetSymbolAddress((void**)&up,   g_up);

    embed_kernel<<<(BT * D_ + 255) / 256, 256>>>(tok, pos, intent, rvq, pe);

    for (int l = 0; l < L_; l++) {
        rmsnorm_kernel<<<BT, 256>>>(x, h, n1 + (size_t)l * D_);

        gemm_kernel<<<dim3(E3 / BNt, BT / BMt), 256>>>(
            h, qkvw + (size_t)l * E3 * D_, qkv, nullptr, BT, E3, D_);

        attn_kernel<<<B_ * H_ * T_, 128>>>();

        gemm_kernel<<<dim3(D_ / BNt, BT / BMt), 256>>>(
            att, projw + (size_t)l * D_ * D_, x, x, BT, D_, D_);

        rmsnorm_kernel<<<BT, 256>>>(x, h, n2 + (size_t)l * D_);

        gemm_kernel<<<dim3(FF_ / BNt, BT / BMt), 256>>>(
            h, gatew + (size_t)l * FF_ * D_, gate, nullptr, BT, FF_, D_);
        gemm_kernel<<<dim3(FF_ / BNt, BT / BMt), 256>>>(
            h, upw + (size_t)l * FF_ * D_, up, nullptr, BT, FF_, D_);

        silu_mul_kernel<<<(BT * FF_ + 255) / 256, 256>>>();

        gemm_kernel<<<dim3(D_ / BNt, BT / BMt), 256>>>(
            gate, downw + (size_t)l * D_ * FF_, x, x, BT, D_, FF_);
    }

    final_norm_kernel<<<B_, 256>>>(nf);
    heads_kernel<<<S_ * B_ * V_, 128>>>(hw, out);
}

// round 2
// speedup vs baseline: 1.5828x; 1.5828x over previous
#include <cuda_runtime.h>
#include <math.h>

#define B_  2
#define T_  1024
#define BT  2048
#define D_  768
#define H_  12
#define DH_ 64
#define FF_ 3072
#define L_  12
#define S_  8
#define V_  1024
#define E3  2304   // 3*D

// ---------------- scratch (static device arrays; no allocation allowed) ----
__device__ __align__(16) float g_x   [BT * D_];
__device__ __align__(16) float g_h   [BT * D_];
__device__ __align__(16) float g_qkv [BT * E3];
__device__ __align__(16) float g_att [BT * D_];
__device__ __align__(16) float g_gate[BT * FF_];
__device__ __align__(16) float g_up  [BT * FF_];
__device__ __align__(16) float g_last[B_ * D_];

// ---------------- embedding ------------------------------------------------
__global__ void embed_kernel(const int* __restrict__ tok,
                             const int* __restrict__ pos,
                             const float* __restrict__ intent,
                             const float* __restrict__ rvq,
                             const float* __restrict__ pe) {
    int i = blockIdx.x * blockDim.x + threadIdx.x;
    if (i >= BT * D_) return;
    int row = i / D_, d = i % D_;
    int b = row / T_;
    float acc = intent[b * D_ + d] + pe[(size_t)pos[row] * D_ + d];
    const int* tk = tok + (size_t)row * S_;
#pragma unroll
    for (int s = 0; s < S_; s++)
        acc += rvq[((size_t)s * V_ + tk[s]) * D_ + d];
    g_x[i] = acc;
}

// ---------------- rmsnorm (one block per row) ------------------------------
__global__ void rmsnorm_kernel(const float* __restrict__ src,
                               float* __restrict__ dst,
                               const float* __restrict__ w) {
    int row = blockIdx.x;
    const float* x = src + (size_t)row * D_;
    __shared__ float red[256];
    float ss = 0.f;
    for (int d = threadIdx.x; d < D_; d += 256) { float v = x[d]; ss += v * v; }
    red[threadIdx.x] = ss;
    __syncthreads();
    for (int s = 128; s > 0; s >>= 1) {
        if (threadIdx.x < s) red[threadIdx.x] += red[threadIdx.x + s];
        __syncthreads();
    }
    float inv = rsqrtf(red[0] * (1.0f / D_) + 1e-6f);
    for (int d = threadIdx.x; d < D_; d += 256)
        dst[(size_t)row * D_ + d] = x[d] * inv * w[d];
}

// ---------------- fp32 GEMM: C[M,N] = (res?) + A[M,K] * W[N,K]^T ----------
// BM=128 fixed, BK=16, 256 threads, 8xTN microtile (TN = BN/16).
template<int BN, int TN>
__global__ __launch_bounds__(256)
void gemm_kernel(const float* __restrict__ A,
                 const float* __restrict__ W,
                 float* __restrict__ C,
                 const float* __restrict__ res,
                 int M, int N, int K) {
    __shared__ float As[16][128 + 4];
    __shared__ float Ws[16][BN + 4];
    int tid = threadIdx.x;
    int tx = tid & 15, ty = tid >> 4;
    int m0 = blockIdx.y * 128, n0 = blockIdx.x * BN;

    float acc[8][TN];
#pragma unroll
    for (int i = 0; i < 8; i++)
#pragma unroll
        for (int j = 0; j < TN; j++) acc[i][j] = 0.f;

    for (int k0 = 0; k0 < K; k0 += 16) {
        // A tile: 128x16 = 512 float4, 2 per thread
#pragma unroll
        for (int i = 0; i < 2; i++) {
            int idx = tid + i * 256;
            int row = idx >> 2, kv = (idx & 3) * 4;
            float4 a = *(const float4*)&A[(size_t)(m0 + row) * K + k0 + kv];
            As[kv + 0][row] = a.x; As[kv + 1][row] = a.y;
            As[kv + 2][row] = a.z; As[kv + 3][row] = a.w;
        }
        // W tile: BNx16 float4s
#pragma unroll
        for (int i = 0; i < BN / 64; i++) {
            int idx = tid + i * 256;
            int row = idx >> 2, kv = (idx & 3) * 4;
            float4 w4 = *(const float4*)&W[(size_t)(n0 + row) * K + k0 + kv];
            Ws[kv + 0][row] = w4.x; Ws[kv + 1][row] = w4.y;
            Ws[kv + 2][row] = w4.z; Ws[kv + 3][row] = w4.w;
        }
        __syncthreads();
#pragma unroll
        for (int kk = 0; kk < 16; kk++) {
            float a[8], w[TN];
            float4 a0 = *(const float4*)&As[kk][ty * 8];
            float4 a1 = *(const float4*)&As[kk][ty * 8 + 4];
            a[0] = a0.x; a[1] = a0.y; a[2] = a0.z; a[3] = a0.w;
            a[4] = a1.x; a[5] = a1.y; a[6] = a1.z; a[7] = a1.w;
            float4 w0 = *(const float4*)&Ws[kk][tx * TN];
            w[0] = w0.x; w[1] = w0.y; w[2] = w0.z; w[3] = w0.w;
            if (TN == 8) {
                float4 w1 = *(const float4*)&Ws[kk][tx * TN + 4];
                w[4] = w1.x; w[5] = w1.y; w[6] = w1.z; w[7] = w1.w;
            }
#pragma unroll
            for (int i = 0; i < 8; i++)
#pragma unroll
                for (int j = 0; j < TN; j++)
                    acc[i][j] += a[i] * w[j];
        }
        __syncthreads();
    }
#pragma unroll
    for (int i = 0; i < 8; i++) {
        int m = m0 + ty * 8 + i;
#pragma unroll
        for (int jv = 0; jv < TN / 4; jv++) {
            size_t off = (size_t)m * N + n0 + tx * TN + jv * 4;
            float4 c = make_float4(acc[i][jv*4+0], acc[i][jv*4+1],
                                   acc[i][jv*4+2], acc[i][jv*4+3]);
            if (res) {
                float4 r = *(const float4*)&res[off];
                c.x += r.x; c.y += r.y; c.z += r.z; c.w += r.w;
            }
            *(float4*)&C[off] = c;
        }
    }
}

// ---------------- flash attention: 128 q-rows per block, online softmax ----
#define TQ 128
#define TK 32
__global__ __launch_bounds__(128)
void attn_kernel() {
    __shared__ float Ks[TK * 68];
    __shared__ float Vs[TK * 68];
    __shared__ float Sc[TQ * 33];

    int bid = blockIdx.x;
    int bh = bid % (B_ * H_);
    int qt = (T_ / TQ - 1) - bid / (B_ * H_);   // heavy tiles launch first
    int h = bh % H_, b = bh / H_;
    int q0 = qt * TQ;
    int tid = threadIdx.x;
    int r = q0 + tid;                            // this thread's query row
    const float* base = g_qkv + (size_t)b * T_ * E3;

    // q into registers
    float4 qv[16], o[16];
    const float4* qp = (const float4*)(base + (size_t)r * E3 + h * DH_);
#pragma unroll
    for (int i = 0; i < 16; i++) { qv[i] = qp[i]; o[i] = make_float4(0.f,0.f,0.f,0.f); }

    float m = -INFINITY, lsum = 0.f;
    int ntiles = q0 / TK + (TQ / TK);

    int lj = tid >> 2, lq = tid & 3;             // tile-load mapping
    for (int t = 0; t < ntiles; t++) {
        int k0 = t * TK;
        __syncthreads();
        {
            const float4* kp = (const float4*)(base + (size_t)(k0 + lj) * E3 +     D_ + h * DH_ + lq * 16);
            const float4* vp = (const float4*)(base + (size_t)(k0 + lj) * E3 + 2 * D_ + h * DH_ + lq * 16);
            float4* kd = (float4*)(Ks + lj * 68 + lq * 16);
            float4* vd = (float4*)(Vs + lj * 68 + lq * 16);
#pragma unroll
            for (int i = 0; i < 4; i++) { kd[i] = kp[i]; vd[i] = vp[i]; }
        }
        __syncthreads();

        bool full = (k0 < q0);
        float smax = -INFINITY;
#pragma unroll 4
        for (int j = 0; j < TK; j++) {
            const float4* krow = (const float4*)(Ks + j * 68);
            float dot = 0.f;
#pragma unroll
            for (int i = 0; i < 16; i++) {
                float4 k4 = krow[i];
                dot += qv[i].x * k4.x + qv[i].y * k4.y + qv[i].z * k4.z + qv[i].w * k4.w;
            }
            float s = dot * 0.125f;
            if (!full && (k0 + j > r)) s = -INFINITY;
            Sc[tid * 33 + j] = s;
            smax = fmaxf(smax, s);
        }
        float newm = fmaxf(m, smax);
        float corr = __expf(m - newm);
        m = newm;
        lsum *= corr;
#pragma unroll
        for (int i = 0; i < 16; i++) {
            o[i].x *= corr; o[i].y *= corr; o[i].z *= corr; o[i].w *= corr;
        }
#pragma unroll 4
        for (int j = 0; j < TK; j++) {
            float e = __expf(Sc[tid * 33 + j] - m);
            lsum += e;
            const float4* vrow = (const float4*)(Vs + j * 68);
#pragma unroll
            for (int i = 0; i < 16; i++) {
                float4 v4 = vrow[i];
                o[i].x += e * v4.x; o[i].y += e * v4.y;
                o[i].z += e * v4.z; o[i].w += e * v4.w;
            }
        }
    }
    float inv = 1.f / lsum;
    float4* op = (float4*)(g_att + (size_t)(b * T_ + r) * D_ + h * DH_);
#pragma unroll
    for (int i = 0; i < 16; i++)
        op[i] = make_float4(o[i].x * inv, o[i].y * inv, o[i].z * inv, o[i].w * inv);
}

// ---------------- silu(gate) * up ------------------------------------------
__global__ void silu_mul_kernel() {
    int i = blockIdx.x * blockDim.x + threadIdx.x;
    if (i >= BT * FF_) return;
    float g = g_gate[i];
    g_gate[i] = (g / (1.f + __expf(-g))) * g_up[i];
}

// ---------------- final rmsnorm on last token rows -------------------------
__global__ void final_norm_kernel(const float* __restrict__ w) {
    int b = blockIdx.x;
    const float* x = g_x + ((size_t)(b * T_ + T_ - 1)) * D_;
    __shared__ float red[256];
    float ss = 0.f;
    for (int d = threadIdx.x; d < D_; d += 256) { float v = x[d]; ss += v * v; }
    red[threadIdx.x] = ss;
    __syncthreads();
    for (int s = 128; s > 0; s >>= 1) {
        if (threadIdx.x < s) red[threadIdx.x] += red[threadIdx.x + s];
        __syncthreads();
    }
    float inv = rsqrtf(red[0] * (1.0f / D_) + 1e-6f);
    for (int d = threadIdx.x; d < D_; d += 256)
        g_last[b * D_ + d] = x[d] * inv * w[d];
}

// ---------------- heads: logits[s,b,v] = last[b,:] . heads_w[s,v,:] --------
__global__ void heads_kernel(const float* __restrict__ hw, float* __restrict__ out) {
    int idx = blockIdx.x;           // (s*B + b)*V + v
    int v = idx % V_;
    int sb = idx / V_;
    int b = sb % B_;
    int s = sb / B_;
    const float* wrow = hw + ((size_t)s * V_ + v) * D_;
    const float* xv = g_last + b * D_;
    float dot = 0.f;
    for (int d = threadIdx.x; d < D_; d += 128) dot += xv[d] * wrow[d];
    __shared__ float red[128];
    red[threadIdx.x] = dot;
    __syncthreads();
    for (int s2 = 64; s2 > 0; s2 >>= 1) {
        if (threadIdx.x < s2) red[threadIdx.x] += red[threadIdx.x + s2];
        __syncthreads();
    }
    if (threadIdx.x == 0) out[idx] = red[0];
}

// ---------------- launcher -------------------------------------------------
extern "C" void kernel_launch(void* const* d_in, const int* in_sizes, int n_in,
                              void* d_out, int out_size) {
    const int*   tok    = (const int*)d_in[0];
    const int*   pos    = (const int*)d_in[1];
    const float* intent = (const float*)d_in[2];
    const float* rvq    = (const float*)d_in[3];
    const float* pe     = (const float*)d_in[4];
    const float* n1     = (const float*)d_in[5];
    const float* n2     = (const float*)d_in[6];
    const float* qkvw   = (const float*)d_in[7];
    const float* projw  = (const float*)d_in[8];
    const float* gatew  = (const float*)d_in[9];
    const float* upw    = (const float*)d_in[10];
    const float* downw  = (const float*)d_in[11];
    const float* nf     = (const float*)d_in[12];
    const float* hw     = (const float*)d_in[13];
    float* out = (float*)d_out;

    float *x, *h, *qkv, *att, *gate, *up;
    cudaGetSymbolAddress((void**)&x,    g_x);
    cudaGetSymbolAddress((void**)&h,    g_h);
    cudaGetSymbolAddress((void**)&qkv,  g_qkv);
    cudaGetSymbolAddress((void**)&att,  g_att);
    cudaGetSymbolAddress((void**)&gate, g_gate);
    cudaGetSymbolAddress((void**)&up,   g_up);

    embed_kernel<<<(BT * D_ + 255) / 256, 256>>>(tok, pos, intent, rvq, pe);

    for (int l = 0; l < L_; l++) {
        rmsnorm_kernel<<<BT, 256>>>(x, h, n1 + (size_t)l * D_);

        gemm_kernel<128, 8><<<dim3(E3 / 128, BT / 128), 256>>>(
            h, qkvw + (size_t)l * E3 * D_, qkv, nullptr, BT, E3, D_);

        attn_kernel<<<B_ * H_ * (T_ / TQ), 128>>>();

        gemm_kernel<64, 4><<<dim3(D_ / 64, BT / 128), 256>>>(
            att, projw + (size_t)l * D_ * D_, x, x, BT, D_, D_);

        rmsnorm_kernel<<<BT, 256>>>(x, h, n2 + (size_t)l * D_);

        gemm_kernel<128, 8><<<dim3(FF_ / 128, BT / 128), 256>>>(
            h, gatew + (size_t)l * FF_ * D_, gate, nullptr, BT, FF_, D_);
        gemm_kernel<128, 8><<<dim3(FF_ / 128, BT / 128), 256>>>(
            h, upw + (size_t)l * FF_ * D_, up, nullptr, BT, FF_, D_);

        silu_mul_kernel<<<(BT * FF_ + 255) / 256, 256>>>();

        gemm_kernel<64, 4><<<dim3(D_ / 64, BT / 128), 256>>>(
            gate, downw + (size_t)l * D_ * FF_, x, x, BT, D_, FF_);
    }

    final_norm_kernel<<<B_, 256>>>(nf);
    heads_kernel<<<S_ * B_ * V_, 128>>>(hw, out);
}

// round 4
// speedup vs baseline: 3.0083x; 1.9007x over previous
#include <cuda_runtime.h>
#include <cuda_bf16.h>
#include <math.h>
#include <stdint.h>

#define B_  2
#define T_  1024
#define BT  2048
#define D_  768
#define H_  12
#define DH_ 64
#define FF_ 3072
#define L_  12
#define S_  8
#define V_  1024
#define E3  2304   // 3*D

typedef __nv_bfloat16 bf16;

// ---------------- scratch (static device arrays) ---------------------------
__device__ __align__(16) float g_x   [BT * D_];
__device__ __align__(16) float g_qkv [BT * E3];
__device__ __align__(16) float g_gate[BT * FF_];
__device__ __align__(16) float g_up  [BT * FF_];
__device__ __align__(16) float g_last[B_ * D_];

__device__ __align__(16) bf16 g_h_hi [BT * D_];
__device__ __align__(16) bf16 g_h_lo [BT * D_];
__device__ __align__(16) bf16 g_at_hi[BT * D_];
__device__ __align__(16) bf16 g_at_lo[BT * D_];
__device__ __align__(16) bf16 g_ff_hi[BT * FF_];
__device__ __align__(16) bf16 g_ff_lo[BT * FF_];

// weight splits
__device__ __align__(16) bf16 g_qkvw_hi [L_ * E3 * D_];
__device__ __align__(16) bf16 g_qkvw_lo [L_ * E3 * D_];
__device__ __align__(16) bf16 g_projw_hi[L_ * D_ * D_];
__device__ __align__(16) bf16 g_projw_lo[L_ * D_ * D_];
__device__ __align__(16) bf16 g_gatew_hi[L_ * FF_ * D_];
__device__ __align__(16) bf16 g_gatew_lo[L_ * FF_ * D_];
__device__ __align__(16) bf16 g_upw_hi  [L_ * FF_ * D_];
__device__ __align__(16) bf16 g_upw_lo  [L_ * FF_ * D_];
__device__ __align__(16) bf16 g_downw_hi[L_ * D_ * FF_];
__device__ __align__(16) bf16 g_downw_lo[L_ * D_ * FF_];

// ---------------- helpers --------------------------------------------------
__device__ __forceinline__ uint32_t smem_u32(const void* p) {
    uint32_t a;
    asm("{ .reg .u64 t; cvta.to.shared.u64 t, %1; cvt.u32.u64 %0, t; }" : "=r"(a) : "l"(p));
    return a;
}
__device__ __forceinline__ void cp16(uint32_t dst, const void* src) {
    asm volatile("cp.async.cg.shared.global [%0], [%1], 16;" :: "r"(dst), "l"(src));
}
__device__ __forceinline__ void cp_commit() {
    asm volatile("cp.async.commit_group;" ::: "memory");
}
template<int N>
__device__ __forceinline__ void cp_wait() {
    asm volatile("cp.async.wait_group %0;" :: "n"(N) : "memory");
}
__device__ __forceinline__ void ldsm4(uint32_t& r0, uint32_t& r1, uint32_t& r2, uint32_t& r3,
                                      uint32_t addr) {
    asm volatile("ldmatrix.sync.aligned.m8n8.x4.shared.b16 {%0,%1,%2,%3}, [%4];"
                 : "=r"(r0), "=r"(r1), "=r"(r2), "=r"(r3) : "r"(addr));
}
__device__ __forceinline__ void mma_bf16(float* c, const uint32_t* a, const uint32_t* b) {
    asm volatile(
        "mma.sync.aligned.m16n8k16.row.col.f32.bf16.bf16.f32 "
        "{%0,%1,%2,%3}, {%4,%5,%6,%7}, {%8,%9}, {%0,%1,%2,%3};"
        : "+f"(c[0]), "+f"(c[1]), "+f"(c[2]), "+f"(c[3])
        : "r"(a[0]), "r"(a[1]), "r"(a[2]), "r"(a[3]), "r"(b[0]), "r"(b[1]));
}
#define SWZ(x) ((x) ^ (((x) >> 3) & 0x70))

// ---------------- split helpers --------------------------------------------
__device__ __forceinline__ void split2(float x, bf16& h, bf16& l) {
    h = __float2bfloat16_rn(x);
    l = __float2bfloat16_rn(x - __bfloat162float(h));
}

__global__ void split_kernel(const float* __restrict__ x,
                             bf16* __restrict__ hi, bf16* __restrict__ lo, int n) {
    int i = blockIdx.x * blockDim.x + threadIdx.x;
    if (i >= n) return;
    bf16 h, l; split2(x[i], h, l);
    hi[i] = h; lo[i] = l;
}

// ---------------- embedding ------------------------------------------------
__global__ void embed_kernel(const int* __restrict__ tok,
                             const int* __restrict__ pos,
                             const float* __restrict__ intent,
                             const float* __restrict__ rvq,
                             const float* __restrict__ pe) {
    int i = blockIdx.x * blockDim.x + threadIdx.x;
    if (i >= BT * D_) return;
    int row = i / D_, d = i % D_;
    int b = row / T_;
    float acc = intent[b * D_ + d] + pe[(size_t)pos[row] * D_ + d];
    const int* tk = tok + (size_t)row * S_;
#pragma unroll
    for (int s = 0; s < S_; s++)
        acc += rvq[((size_t)s * V_ + tk[s]) * D_ + d];
    g_x[i] = acc;
}

// ---------------- rmsnorm -> hi/lo bf16 ------------------------------------
__global__ void rmsnorm_split_kernel(const float* __restrict__ src,
                                     const float* __restrict__ w,
                                     bf16* __restrict__ hi, bf16* __restrict__ lo) {
    int row = blockIdx.x;
    const float* x = src + (size_t)row * D_;
    __shared__ float red[256];
    float ss = 0.f;
    for (int d = threadIdx.x; d < D_; d += 256) { float v = x[d]; ss += v * v; }
    red[threadIdx.x] = ss;
    __syncthreads();
    for (int s = 128; s > 0; s >>= 1) {
        if (threadIdx.x < s) red[threadIdx.x] += red[threadIdx.x + s];
        __syncthreads();
    }
    float inv = rsqrtf(red[0] * (1.0f / D_) + 1e-6f);
    for (int d = threadIdx.x; d < D_; d += 256) {
        float y = x[d] * inv * w[d];
        bf16 h, l; split2(y, h, l);
        hi[(size_t)row * D_ + d] = h;
        lo[(size_t)row * D_ + d] = l;
    }
}

// ---------------- HMMA bf16x3 GEMM: C = (res?) + A * W^T -------------------
// A:[M,K] hi/lo bf16 row-major. W:[N,K] hi/lo bf16 row-major. C fp32 [M,N].
// 128x128 CTA tile, BK=64, 256 threads (8 warps: 4m x 2n), double-buffered cp.async.
#define STG 16384                     // bytes per tile array per stage
#define GSMEM (2 * 4 * STG)           // 131072
__global__ __launch_bounds__(256)
void gemm_mma(const bf16* __restrict__ Ah, const bf16* __restrict__ Al,
              const bf16* __restrict__ Wh, const bf16* __restrict__ Wl,
              float* __restrict__ C, const float* __restrict__ res,
              int N, int K) {
    extern __shared__ char smem[];
    uint32_t sb = smem_u32(smem);
    int tid = threadIdx.x, lane = tid & 31, w = tid >> 5;
    int mw = w >> 1, nw = w & 1;
    int m0 = blockIdx.y * 128, n0 = blockIdx.x * 128;

    float c[2][8][4];
#pragma unroll
    for (int i = 0; i < 2; i++)
#pragma unroll
        for (int j = 0; j < 8; j++)
#pragma unroll
            for (int q = 0; q < 4; q++) c[i][j][q] = 0.f;

    int nst = K >> 6;

    // ldmatrix lane-address components (byte offsets within a tile array)
    int a_row = (lane & 15);
    int a_kof = (lane >> 4) * 16;
    int b_row = (lane & 7) + ((lane >> 4) << 3);
    int b_kof = ((lane >> 3) & 1) * 16;

    // ---- prologue: load stage 0
    {
        int k0 = 0;
        uint32_t buf = sb;
#pragma unroll
        for (int j = 0; j < 4; j++) {
            int idx = tid + j * 256;
            int row = idx >> 3, q = idx & 7;
            uint32_t so = SWZ(row * 128 + q * 16);
            size_t ga = (size_t)(m0 + row) * K + k0 + q * 8;
            size_t gw = (size_t)(n0 + row) * K + k0 + q * 8;
            cp16(buf + 0 * STG + so, Ah + ga);
            cp16(buf + 1 * STG + so, Al + ga);
            cp16(buf + 2 * STG + so, Wh + gw);
            cp16(buf + 3 * STG + so, Wl + gw);
        }
        cp_commit();
    }

    for (int i = 0; i < nst; i++) {
        if (i + 1 < nst) {
            int k0 = (i + 1) << 6;
            uint32_t buf = sb + ((i + 1) & 1) * (4 * STG);
#pragma unroll
            for (int j = 0; j < 4; j++) {
                int idx = tid + j * 256;
                int row = idx >> 3, q = idx & 7;
                uint32_t so = SWZ(row * 128 + q * 16);
                size_t ga = (size_t)(m0 + row) * K + k0 + q * 8;
                size_t gw = (size_t)(n0 + row) * K + k0 + q * 8;
                cp16(buf + 0 * STG + so, Ah + ga);
                cp16(buf + 1 * STG + so, Al + ga);
                cp16(buf + 2 * STG + so, Wh + gw);
                cp16(buf + 3 * STG + so, Wl + gw);
            }
            cp_commit();
            cp_wait<1>();
        } else {
            cp_wait<0>();
        }
        __syncthreads();

        uint32_t buf = sb + (i & 1) * (4 * STG);
        uint32_t sAh = buf, sAl = buf + STG, sWh = buf + 2 * STG, sWl = buf + 3 * STG;

#pragma unroll
        for (int ks = 0; ks < 4; ks++) {
            uint32_t ah[2][4], al[2][4], bh[8][2], bl[8][2];
#pragma unroll
            for (int mt = 0; mt < 2; mt++) {
                uint32_t off = SWZ((mw * 32 + mt * 16 + a_row) * 128 + ks * 32 + a_kof);
                ldsm4(ah[mt][0], ah[mt][1], ah[mt][2], ah[mt][3], sAh + off);
                ldsm4(al[mt][0], al[mt][1], al[mt][2], al[mt][3], sAl + off);
            }
#pragma unroll
            for (int p = 0; p < 4; p++) {
                uint32_t off = SWZ((nw * 64 + p * 16 + b_row) * 128 + ks * 32 + b_kof);
                ldsm4(bh[2*p][0], bh[2*p][1], bh[2*p+1][0], bh[2*p+1][1], sWh + off);
                ldsm4(bl[2*p][0], bl[2*p][1], bl[2*p+1][0], bl[2*p+1][1], sWl + off);
            }
#pragma unroll
            for (int mt = 0; mt < 2; mt++)
#pragma unroll
                for (int nt = 0; nt < 8; nt++) {
                    mma_bf16(c[mt][nt], ah[mt], bh[nt]);
                    mma_bf16(c[mt][nt], ah[mt], bl[nt]);
                    mma_bf16(c[mt][nt], al[mt], bh[nt]);
                }
        }
        __syncthreads();
    }

    // ---- epilogue
    int g = lane >> 2, tig = lane & 3;
#pragma unroll
    for (int mt = 0; mt < 2; mt++) {
        int row = m0 + mw * 32 + mt * 16 + g;
#pragma unroll
        for (int nt = 0; nt < 8; nt++) {
            int col = n0 + nw * 64 + nt * 8 + tig * 2;
            size_t o0 = (size_t)row * N + col;
            size_t o1 = o0 + (size_t)8 * N;
            float2 v0 = make_float2(c[mt][nt][0], c[mt][nt][1]);
            float2 v1 = make_float2(c[mt][nt][2], c[mt][nt][3]);
            if (res) {
                float2 r0 = *(const float2*)&res[o0];
                float2 r1 = *(const float2*)&res[o1];
                v0.x += r0.x; v0.y += r0.y; v1.x += r1.x; v1.y += r1.y;
            }
            *(float2*)&C[o0] = v0;
            *(float2*)&C[o1] = v1;
        }
    }
}

// ---------------- flash attention: TQ=64 rows/block, 64 threads ------------
#define TQ 64
#define TK 32
__global__ __launch_bounds__(64)
void attn_kernel() {
    __shared__ float Ks[TK * 68];
    __shared__ float Vs[TK * 68];
    __shared__ float Sc[TQ * 33];

    int bid = blockIdx.x;
    int bh = bid % (B_ * H_);
    int qt = (T_ / TQ - 1) - bid / (B_ * H_);   // heavy tiles first
    int h = bh % H_, b = bh / H_;
    int q0 = qt * TQ;
    int tid = threadIdx.x;
    int r = q0 + tid;
    const float* base = g_qkv + (size_t)b * T_ * E3;

    float4 qv[16], o[16];
    const float4* qp = (const float4*)(base + (size_t)r * E3 + h * DH_);
#pragma unroll
    for (int i = 0; i < 16; i++) { qv[i] = qp[i]; o[i] = make_float4(0.f, 0.f, 0.f, 0.f); }

    float m = -INFINITY, lsum = 0.f;
    int ntiles = q0 / TK + (TQ / TK);

    for (int t = 0; t < ntiles; t++) {
        int k0 = t * TK;
        __syncthreads();
#pragma unroll
        for (int i = 0; i < 8; i++) {
            int idx = tid + i * 64;
            int row = idx >> 4, col = idx & 15;
            const float4* kp = (const float4*)(base + (size_t)(k0 + row) * E3 + D_ + h * DH_);
            const float4* vp = (const float4*)(base + (size_t)(k0 + row) * E3 + 2 * D_ + h * DH_);
            *(float4*)(Ks + row * 68 + col * 4) = kp[col];
            *(float4*)(Vs + row * 68 + col * 4) = vp[col];
        }
        __syncthreads();

        bool full = (k0 < q0);
        float smax = -INFINITY;
#pragma unroll 4
        for (int j = 0; j < TK; j++) {
            const float4* krow = (const float4*)(Ks + j * 68);
            float dot = 0.f;
#pragma unroll
            for (int i = 0; i < 16; i++) {
                float4 k4 = krow[i];
                dot += qv[i].x * k4.x + qv[i].y * k4.y + qv[i].z * k4.z + qv[i].w * k4.w;
            }
            float s = dot * 0.125f;
            if (!full && (k0 + j > r)) s = -INFINITY;
            Sc[tid * 33 + j] = s;
            smax = fmaxf(smax, s);
        }
        float newm = fmaxf(m, smax);
        float corr = __expf(m - newm);
        m = newm;
        lsum *= corr;
#pragma unroll
        for (int i = 0; i < 16; i++) {
            o[i].x *= corr; o[i].y *= corr; o[i].z *= corr; o[i].w *= corr;
        }
#pragma unroll 4
        for (int j = 0; j < TK; j++) {
            float e = __expf(Sc[tid * 33 + j] - m);
            lsum += e;
            const float4* vrow = (const float4*)(Vs + j * 68);
#pragma unroll
            for (int i = 0; i < 16; i++) {
                float4 v4 = vrow[i];
                o[i].x += e * v4.x; o[i].y += e * v4.y;
                o[i].z += e * v4.z; o[i].w += e * v4.w;
            }
        }
    }
    float inv = 1.f / lsum;
    size_t ob = (size_t)(b * T_ + r) * D_ + h * DH_;
#pragma unroll
    for (int i = 0; i < 16; i++) {
        float vals[4] = {o[i].x * inv, o[i].y * inv, o[i].z * inv, o[i].w * inv};
#pragma unroll
        for (int cc = 0; cc < 4; cc++) {
            bf16 hh, ll; split2(vals[cc], hh, ll);
            g_at_hi[ob + i * 4 + cc] = hh;
            g_at_lo[ob + i * 4 + cc] = ll;
        }
    }
}

// ---------------- silu(gate) * up -> hi/lo ---------------------------------
__global__ void silu_mul_split_kernel() {
    int i = blockIdx.x * blockDim.x + threadIdx.x;
    if (i >= BT * FF_) return;
    float g = g_gate[i];
    float y = (g / (1.f + __expf(-g))) * g_up[i];
    bf16 h, l; split2(y, h, l);
    g_ff_hi[i] = h; g_ff_lo[i] = l;
}

// ---------------- final rmsnorm on last token rows -------------------------
__global__ void final_norm_kernel(const float* __restrict__ w) {
    int b = blockIdx.x;
    const float* x = g_x + ((size_t)(b * T_ + T_ - 1)) * D_;
    __shared__ float red[256];
    float ss = 0.f;
    for (int d = threadIdx.x; d < D_; d += 256) { float v = x[d]; ss += v * v; }
    red[threadIdx.x] = ss;
    __syncthreads();
    for (int s = 128; s > 0; s >>= 1) {
        if (threadIdx.x < s) red[threadIdx.x] += red[threadIdx.x + s];
        __syncthreads();
    }
    float inv = rsqrtf(red[0] * (1.0f / D_) + 1e-6f);
    for (int d = threadIdx.x; d < D_; d += 256)
        g_last[b * D_ + d] = x[d] * inv * w[d];
}

// ---------------- heads ----------------------------------------------------
__global__ void heads_kernel(const float* __restrict__ hw, float* __restrict__ out) {
    int idx = blockIdx.x;
    int v = idx % V_;
    int sb = idx / V_;
    int b = sb % B_;
    int s = sb / B_;
    const float* wrow = hw + ((size_t)s * V_ + v) * D_;
    const float* xv = g_last + b * D_;
    float dot = 0.f;
    for (int d = threadIdx.x; d < D_; d += 128) dot += xv[d] * wrow[d];
    __shared__ float red[128];
    red[threadIdx.x] = dot;
    __syncthreads();
    for (int s2 = 64; s2 > 0; s2 >>= 1) {
        if (threadIdx.x < s2) red[threadIdx.x] += red[threadIdx.x + s2];
        __syncthreads();
    }
    if (threadIdx.x == 0) out[idx] = red[0];
}

// ---------------- launcher -------------------------------------------------
extern "C" void kernel_launch(void* const* d_in, const int* in_sizes, int n_in,
                              void* d_out, int out_size) {
    const int*   tok    = (const int*)d_in[0];
    const int*   pos    = (const int*)d_in[1];
    const float* intent = (const float*)d_in[2];
    const float* rvq    = (const float*)d_in[3];
    const float* pe     = (const float*)d_in[4];
    const float* n1     = (const float*)d_in[5];
    const float* n2     = (const float*)d_in[6];
    const float* qkvw   = (const float*)d_in[7];
    const float* projw  = (const float*)d_in[8];
    const float* gatew  = (const float*)d_in[9];
    const float* upw    = (const float*)d_in[10];
    const float* downw  = (const float*)d_in[11];
    const float* nf     = (const float*)d_in[12];
    const float* hw     = (const float*)d_in[13];
    float* out = (float*)d_out;

    static int smem_set = 0;
    if (!smem_set) {
        cudaFuncSetAttribute(gemm_mma, cudaFuncAttributeMaxDynamicSharedMemorySize, GSMEM);
        smem_set = 1;
    }

    float *x, *qkv, *gate, *up;
    bf16 *h_hi, *h_lo, *at_hi, *at_lo, *ff_hi, *ff_lo;
    bf16 *qw_h, *qw_l, *pw_h, *pw_l, *gw_h, *gw_l, *uw_h, *uw_l, *dw_h, *dw_l;
    cudaGetSymbolAddress((void**)&x,    g_x);
    cudaGetSymbolAddress((void**)&qkv,  g_qkv);
    cudaGetSymbolAddress((void**)&gate, g_gate);
    cudaGetSymbolAddress((void**)&up,   g_up);
    cudaGetSymbolAddress((void**)&h_hi, g_h_hi);
    cudaGetSymbolAddress((void**)&h_lo, g_h_lo);
    cudaGetSymbolAddress((void**)&at_hi, g_at_hi);
    cudaGetSymbolAddress((void**)&at_lo, g_at_lo);
    cudaGetSymbolAddress((void**)&ff_hi, g_ff_hi);
    cudaGetSymbolAddress((void**)&ff_lo, g_ff_lo);
    cudaGetSymbolAddress((void**)&qw_h, g_qkvw_hi);
    cudaGetSymbolAddress((void**)&qw_l, g_qkvw_lo);
    cudaGetSymbolAddress((void**)&pw_h, g_projw_hi);
    cudaGetSymbolAddress((void**)&pw_l, g_projw_lo);
    cudaGetSymbolAddress((void**)&gw_h, g_gatew_hi);
    cudaGetSymbolAddress((void**)&gw_l, g_gatew_lo);
    cudaGetSymbolAddress((void**)&uw_h, g_upw_hi);
    cudaGetSymbolAddress((void**)&uw_l, g_upw_lo);
    cudaGetSymbolAddress((void**)&dw_h, g_downw_hi);
    cudaGetSymbolAddress((void**)&dw_l, g_downw_lo);

    // weight conversion (every replay; deterministic)
    {
        int n;
        n = L_ * E3 * D_;  split_kernel<<<(n + 255) / 256, 256>>>(qkvw,  qw_h, qw_l, n);
        n = L_ * D_ * D_;  split_kernel<<<(n + 255) / 256, 256>>>(projw, pw_h, pw_l, n);
        n = L_ * FF_ * D_; split_kernel<<<(n + 255) / 256, 256>>>(gatew, gw_h, gw_l, n);
        n = L_ * FF_ * D_; split_kernel<<<(n + 255) / 256, 256>>>(upw,   uw_h, uw_l, n);
        n = L_ * D_ * FF_; split_kernel<<<(n + 255) / 256, 256>>>(downw, dw_h, dw_l, n);
    }

    embed_kernel<<<(BT * D_ + 255) / 256, 256>>>(tok, pos, intent, rvq, pe);

    for (int l = 0; l < L_; l++) {
        rmsnorm_split_kernel<<<BT, 256>>>(x, n1 + (size_t)l * D_, h_hi, h_lo);

        gemm_mma<<<dim3(E3 / 128, BT / 128), 256, GSMEM>>>(
            h_hi, h_lo,
            qw_h + (size_t)l * E3 * D_, qw_l + (size_t)l * E3 * D_,
            qkv, nullptr, E3, D_);

        attn_kernel<<<B_ * H_ * (T_ / TQ), 64>>>();

        gemm_mma<<<dim3(D_ / 128, BT / 128), 256, GSMEM>>>(
            at_hi, at_lo,
            pw_h + (size_t)l * D_ * D_, pw_l + (size_t)l * D_ * D_,
            x, x, D_, D_);

        rmsnorm_split_kernel<<<BT, 256>>>(x, n2 + (size_t)l * D_, h_hi, h_lo);

        gemm_mma<<<dim3(FF_ / 128, BT / 128), 256, GSMEM>>>(
            h_hi, h_lo,
            gw_h + (size_t)l * FF_ * D_, gw_l + (size_t)l * FF_ * D_,
            gate, nullptr, FF_, D_);
        gemm_mma<<<dim3(FF_ / 128, BT / 128), 256, GSMEM>>>(
            h_hi, h_lo,
            uw_h + (size_t)l * FF_ * D_, uw_l + (size_t)l * FF_ * D_,
            up, nullptr, FF_, D_);

        silu_mul_split_kernel<<<(BT * FF_ + 255) / 256, 256>>>();

        gemm_mma<<<dim3(D_ / 128, BT / 128), 256, GSMEM>>>(
            ff_hi, ff_lo,
            dw_h + (size_t)l * D_ * FF_, dw_l + (size_t)l * D_ * FF_,
            x, x, D_, FF_);
    }

    final_norm_kernel<<<B_, 256>>>(nf);
    heads_kernel<<<S_ * B_ * V_, 128>>>(hw, out);
}